// round 11
// baseline (speedup 1.0000x reference)
#include <cuda_runtime.h>
#include <math.h>

#define NF 16384
#define NB 4096
#define EF 262144
#define EB 65536

struct __align__(16) EdgeRec { int src; float tu; float tv; int cell; };

__device__ float g_H[(size_t)NF * 4096];   // 256 MB scratch: H = X @ W_all
__device__ float g_X1[NF * 96];
__device__ float g_X2[NF * 64];
__device__ float g_X3[NF * 64];
__device__ float g_Yb[NF * 64];
__device__ float g_Wt[96 * 4096];
__device__ int   g_cntf[NF], g_offf[NF + 1], g_curf[NF];
__device__ int   g_cntb[NF], g_offb[NF + 1], g_curb[NF];
__device__ EdgeRec g_ef[EF];
__device__ EdgeRec g_eb[EB];

__device__ __forceinline__ float tf32r(float x) {
    float y;
    asm("cvt.rna.tf32.f32 %0, %1;" : "=f"(y) : "f"(x));
    return y;
}

// ---------------- CSR build ----------------
__global__ void resetCnt(int* a, int* b) {
    int id = blockIdx.x * blockDim.x + threadIdx.x;
    if (id < NF) { a[id] = 0; b[id] = 0; }
}

__global__ void histAll(const int* __restrict__ fi, const int* __restrict__ bfm,
                        int* __restrict__ cf, int* __restrict__ cb) {
    int e = blockIdx.x * blockDim.x + threadIdx.x;
    if (e < EF) atomicAdd(&cf[fi[e]], 1);
    else if (e < EF + EB) atomicAdd(&cb[bfm[e - EF]], 1);
}

// both scans in ONE launch: block 0 -> fluid, block 1 -> boundary
__global__ void scan2(const int* __restrict__ cf, int* __restrict__ of, int* __restrict__ uf,
                      const int* __restrict__ cb, int* __restrict__ ob, int* __restrict__ ub) {
    const int* cnt = blockIdx.x ? cb : cf;
    int* offs = blockIdx.x ? ob : of;
    int* cur  = blockIdx.x ? ub : uf;
    __shared__ int wsum[32];
    int t = threadIdx.x;
    int lane = t & 31, warp = t >> 5;
    int base = t * 16;
    int local[16];
    int sum = 0;
#pragma unroll
    for (int j = 0; j < 16; j++) { local[j] = sum; sum += cnt[base + j]; }
    int inc = sum;
#pragma unroll
    for (int o = 1; o < 32; o <<= 1) {
        int v = __shfl_up_sync(0xffffffffu, inc, o);
        if (lane >= o) inc += v;
    }
    if (lane == 31) wsum[warp] = inc;
    __syncthreads();
    if (warp == 0) {
        int w = wsum[lane];
#pragma unroll
        for (int o = 1; o < 32; o <<= 1) {
            int v = __shfl_up_sync(0xffffffffu, w, o);
            if (lane >= o) w += v;
        }
        wsum[lane] = w;
    }
    __syncthreads();
    int pre = inc - sum + (warp ? wsum[warp - 1] : 0);
#pragma unroll
    for (int j = 0; j < 16; j++) {
        int o = pre + local[j];
        offs[base + j] = o;
        cur[base + j]  = o;
    }
    if (t == 1023) offs[NF] = pre + sum;
}

// Edge direction EXACTLY as the reference computes it, including signed zeros:
//   fluid:    d = -(fp[src] - fp[tgt]) / support
//   boundary: d =  (bp[src] - fp[tgt]) / support
// Self-edges on the fluid path give (-0,-0): arctan2(-0,-0) = -pi (cell v=0).
__global__ void buildAll(const int* __restrict__ fi, const int* __restrict__ fj,
                         const int* __restrict__ bfm, const int* __restrict__ bb,
                         const float* __restrict__ fp, const float* __restrict__ bp,
                         const float* __restrict__ supPtr,
                         int* __restrict__ curf, EdgeRec* __restrict__ ef,
                         int* __restrict__ curb, EdgeRec* __restrict__ eb) {
    int e = blockIdx.x * blockDim.x + threadIdx.x;
    if (e >= EF + EB) return;
    int t, s, negate;
    const float *tp, *sp;
    int* cur;
    EdgeRec* recs;
    if (e < EF) {
        t = fi[e]; s = fj[e]; tp = fp; sp = fp; negate = 1; cur = curf; recs = ef;
    } else {
        int eb2 = e - EF;
        t = bfm[eb2]; s = bb[eb2]; tp = fp; sp = bp; negate = 0; cur = curb; recs = eb;
    }
    float sup = supPtr[0];
    float bx = sp[2 * s]     - tp[2 * t];      // src - tgt
    float by = sp[2 * s + 1] - tp[2 * t + 1];
    if (negate) { bx = -bx; by = -by; }        // exact IEEE negation: +0 -> -0
    float dx = bx / sup;
    float dy = by / sup;
    dx = fminf(fmaxf(dx, -1.f), 1.f);
    dy = fminf(fmaxf(dy, -1.f), 1.f);
    float r = sqrtf(dx * dx + dy * dy + 1e-12f);
    float u = 2.f * r - 1.f;
    float theta;
    if (dx == 0.f && dy == 0.f) {
        theta = (__float_as_int(dx) < 0) ? copysignf(3.14159265358979323846f, dy)
                                         : copysignf(0.f, dy);
    } else {
        theta = atan2f(dy, dx);
    }
    float v = theta / 3.14159265358979323846f;
    EdgeRec rec;
    rec.src  = s;
    rec.tu   = (u + 1.f) * 3.5f;
    rec.tv   = (v + 1.f) * 3.5f;
    rec.cell = 0;
    int pos = atomicAdd(&cur[t], 1);
    recs[pos] = rec;
}

// ---------------- generic weight transpose: Wt[c*(64*cout)+k*cout+o] = W[k,c,o]
__global__ void transW(const float* __restrict__ W, float* __restrict__ Wt,
                       int cin, int cout, int n) {
    int id = blockIdx.x * blockDim.x + threadIdx.x;
    if (id >= n) return;
    int o = id % cout;
    int rest = id / cout;
    int k = rest & 63;
    int c = rest >> 6;
    Wt[id] = W[(k * cin + c) * cout + o];
}

// ---------------- layer-1 conv: cin=4, cout=32, weights in smem --------------
__global__ __launch_bounds__(256) void conv4(const EdgeRec* __restrict__ recs,
                                             const int* __restrict__ offs,
                                             const float* __restrict__ xsrc,
                                             const float* __restrict__ W,   // [64][4][32]
                                             const float* __restrict__ xt,
                                             const float* __restrict__ fc0,
                                             float* __restrict__ dst, int dstOff) {
    __shared__ float Ws[8192];
    __shared__ float F0[128];
    for (int t = threadIdx.x; t < 8192; t += 256) Ws[t] = W[t];
    if (xt && threadIdx.x < 128) F0[threadIdx.x] = fc0[threadIdx.x];
    __syncthreads();
    int i = blockIdx.x * 8 + (threadIdx.x >> 5);
    int lane = threadIdx.x & 31;
    if (i >= NF) return;
    float y = 0.f;
    int pe = offs[i + 1];
    for (int p = offs[i]; p < pe; ++p) {
        int4 rv = *(const int4*)&recs[p];
        float tu = __int_as_float(rv.y), tv = __int_as_float(rv.z);
        int iu = min(max((int)tu, 0), 6);
        int iv = min(max((int)tv, 0), 6);
        float4 x = *(const float4*)&xsrc[rv.x * 4];
#pragma unroll
        for (int du = 0; du <= 1; du++) {
            float wu = fmaxf(0.f, 1.f - fabsf(tu - (float)(iu + du)));
#pragma unroll
            for (int dv = 0; dv <= 1; dv++) {
                float w = wu * fmaxf(0.f, 1.f - fabsf(tv - (float)(iv + dv)));
                const float* ws = &Ws[((iu + du) * 8 + (iv + dv)) * 128];
                y += w * (x.x * ws[lane] + x.y * ws[32 + lane]
                        + x.z * ws[64 + lane] + x.w * ws[96 + lane]);
            }
        }
    }
    dst[i * 96 + dstOff + lane] = fmaxf(y, 0.f);
    if (xt) {
        float4 x = *(const float4*)&xt[i * 4];
        float yl = x.x * F0[lane] + x.y * F0[32 + lane]
                 + x.z * F0[64 + lane] + x.w * F0[96 + lane];
        dst[i * 96 + lane] = fmaxf(yl, 0.f);
    }
}

// generic bias GEMM (layer-4 only)
__global__ void gemmBias(const float* __restrict__ X, const float* __restrict__ F,
                         float* __restrict__ Y, int K, int cout, int total) {
    int id = blockIdx.x * blockDim.x + threadIdx.x;
    if (id >= total) return;
    int i = id / cout, o = id - i * cout;
    const float* x = X + (size_t)i * K;
    float y = 0.f;
#pragma unroll 4
    for (int c = 0; c < K; c++) y += x[c] * F[c * cout + o];
    Y[id] = y;
}

// ---------------- 1xTF32 tensor-core GEMM: C[M,N] = A[M,K] @ B[K,N] ------------
// Block 128x128, 8 warps of 64x32. Single-pass tf32 (fp32 accumulate).
// Measured deviation vs fp32 reference: ~4e-4 (R5 quadrature) << 1e-3 threshold.
// Requires M%128==0, N%128==0, K%32==0.
__device__ __forceinline__ void mma8(float d[4], const unsigned a[4], const unsigned b[2]) {
    asm volatile("mma.sync.aligned.m16n8k8.row.col.f32.tf32.tf32.f32 "
                 "{%0,%1,%2,%3}, {%4,%5,%6,%7}, {%8,%9}, {%0,%1,%2,%3};"
                 : "+f"(d[0]), "+f"(d[1]), "+f"(d[2]), "+f"(d[3])
                 : "r"(a[0]), "r"(a[1]), "r"(a[2]), "r"(a[3]),
                   "r"(b[0]), "r"(b[1]));
}

#define TGBK 32
#define TGPAD 136
__global__ __launch_bounds__(256) void tf32gemm(int M, int N, int K,
                                                const float* __restrict__ A,
                                                const float* __restrict__ B,
                                                float* __restrict__ C) {
    __shared__ float Ah[TGBK][TGPAD];
    __shared__ float Bh[TGBK][TGPAD];
    int tid = threadIdx.x;
    int bm = blockIdx.y * 128, bn = blockIdx.x * 128;
    int w = tid >> 5, lane = tid & 31;
    int wm = (w & 1) * 64, wn = (w >> 1) * 32;
    int r = lane >> 2, c = lane & 3;
    float acc[4][4][4];
#pragma unroll
    for (int mt = 0; mt < 4; mt++)
#pragma unroll
        for (int nt = 0; nt < 4; nt++)
#pragma unroll
            for (int q = 0; q < 4; q++) acc[mt][nt][q] = 0.f;

    int arow = tid & 127, akq = (tid >> 7) * 16;  // A: 128 rows x 32 k (16/thread)
    int bk = tid >> 3, bnq = (tid & 7) * 16;      // B: 32 k x 128 n  (16/thread)

    for (int k0 = 0; k0 < K; k0 += TGBK) {
        // stage A (transposed to [k][m]), tf32-quantized
        {
            const float* ap = A + (size_t)(bm + arow) * K + k0 + akq;
#pragma unroll
            for (int q = 0; q < 4; q++) {
                float4 v = *(const float4*)(ap + q * 4);
                Ah[akq + q * 4 + 0][arow] = tf32r(v.x);
                Ah[akq + q * 4 + 1][arow] = tf32r(v.y);
                Ah[akq + q * 4 + 2][arow] = tf32r(v.z);
                Ah[akq + q * 4 + 3][arow] = tf32r(v.w);
            }
        }
        // stage B ([k][n]), tf32-quantized
        {
            const float* bp = B + (size_t)(k0 + bk) * N + bn + bnq;
#pragma unroll
            for (int q = 0; q < 4; q++) {
                float4 v = *(const float4*)(bp + q * 4);
                *(float4*)&Bh[bk][bnq + q * 4] =
                    make_float4(tf32r(v.x), tf32r(v.y), tf32r(v.z), tf32r(v.w));
            }
        }
        __syncthreads();

#pragma unroll
        for (int ks = 0; ks < TGBK; ks += 8) {
            unsigned af[4][4], bf[4][2];
#pragma unroll
            for (int mt = 0; mt < 4; mt++) {
                int m = wm + mt * 16 + r;
                af[mt][0] = __float_as_uint(Ah[ks + c][m]);
                af[mt][1] = __float_as_uint(Ah[ks + c][m + 8]);
                af[mt][2] = __float_as_uint(Ah[ks + c + 4][m]);
                af[mt][3] = __float_as_uint(Ah[ks + c + 4][m + 8]);
            }
#pragma unroll
            for (int nt = 0; nt < 4; nt++) {
                int n = wn + nt * 8 + r;
                bf[nt][0] = __float_as_uint(Bh[ks + c][n]);
                bf[nt][1] = __float_as_uint(Bh[ks + c + 4][n]);
            }
#pragma unroll
            for (int mt = 0; mt < 4; mt++)
#pragma unroll
                for (int nt = 0; nt < 4; nt++) mma8(acc[mt][nt], af[mt], bf[nt]);
        }
        __syncthreads();
    }
#pragma unroll
    for (int mt = 0; mt < 4; mt++)
#pragma unroll
        for (int nt = 0; nt < 4; nt++) {
            int m0 = bm + wm + mt * 16 + r;
            int n0 = bn + wn + nt * 8 + 2 * c;
            float* cp = C + (size_t)m0 * N + n0;
            *(float2*)cp = make_float2(acc[mt][nt][0], acc[mt][nt][1]);
            float* cp2 = C + (size_t)(m0 + 8) * N + n0;
            *(float2*)cp2 = make_float2(acc[mt][nt][2], acc[mt][nt][3]);
        }
}

// ---------------- scatter for COUT=64 with FUSED bias GEMM --------------------
__global__ __launch_bounds__(256) void scatter64F(const EdgeRec* __restrict__ recs,
                                                  const int* __restrict__ offs,
                                                  const float* __restrict__ H,
                                                  const float* __restrict__ Xb,
                                                  const float* __restrict__ F, int KB,
                                                  const float* __restrict__ resid,
                                                  float* __restrict__ out) {
    __shared__ float Fs[96 * 64];
    for (int t = threadIdx.x; t < KB * 64; t += 256) Fs[t] = F[t];
    __syncthreads();
    int i = blockIdx.x * 8 + (threadIdx.x >> 5);
    int lane = threadIdx.x & 31;
    if (i >= NF) return;
    float y0 = 0.f, y1 = 0.f;
    int pe = offs[i + 1];
#pragma unroll 2
    for (int p = offs[i]; p < pe; ++p) {
        int4 rv = *(const int4*)&recs[p];
        float tu = __int_as_float(rv.y), tv = __int_as_float(rv.z);
        int iu = min(max((int)tu, 0), 6);
        int iv = min(max((int)tv, 0), 6);
        const float* hb = H + (size_t)rv.x * 4096;
#pragma unroll
        for (int du = 0; du <= 1; du++) {
            float wu = fmaxf(0.f, 1.f - fabsf(tu - (float)(iu + du)));
#pragma unroll
            for (int dv = 0; dv <= 1; dv++) {
                float w = wu * fmaxf(0.f, 1.f - fabsf(tv - (float)(iv + dv)));
                const float* h = hb + ((iu + du) * 8 + (iv + dv)) * 64;
                y0 += w * h[lane];
                y1 += w * h[lane + 32];
            }
        }
    }
    const float* x = Xb + (size_t)i * KB;
    for (int cc = 0; cc < KB; cc++) {
        float xv = x[cc];
        y0 += xv * Fs[cc * 64 + lane];
        y1 += xv * Fs[cc * 64 + lane + 32];
    }
    if (resid) { y0 += resid[i * 64 + lane]; y1 += resid[i * 64 + lane + 32]; }
    out[i * 64 + lane]      = fmaxf(y0, 0.f);
    out[i * 64 + lane + 32] = fmaxf(y1, 0.f);
}

// ---------------- scatter for COUT=2 (layer 4), precomputed bias, no relu ------
__global__ __launch_bounds__(256) void scatter2(const EdgeRec* __restrict__ recs,
                                                const int* __restrict__ offs,
                                                const float* __restrict__ H,
                                                const float* __restrict__ bias,
                                                float* __restrict__ out) {
    int i = blockIdx.x * 8 + (threadIdx.x >> 5);
    int lane = threadIdx.x & 31;
    if (i >= NF) return;
    float y0 = 0.f, y1 = 0.f;
    int pe = offs[i + 1];
    for (int p = offs[i] + lane; p < pe; p += 32) {
        int4 rv = *(const int4*)&recs[p];
        float tu = __int_as_float(rv.y), tv = __int_as_float(rv.z);
        int iu = min(max((int)tu, 0), 6);
        int iv = min(max((int)tv, 0), 6);
        const float* hb = H + (size_t)rv.x * 128;
#pragma unroll
        for (int du = 0; du <= 1; du++) {
            float wu = fmaxf(0.f, 1.f - fabsf(tu - (float)(iu + du)));
#pragma unroll
            for (int dv = 0; dv <= 1; dv++) {
                float w = wu * fmaxf(0.f, 1.f - fabsf(tv - (float)(iv + dv)));
                const float* h = hb + ((iu + du) * 8 + (iv + dv)) * 2;
                y0 += w * h[0];
                y1 += w * h[1];
            }
        }
    }
#pragma unroll
    for (int o = 16; o > 0; o >>= 1) {
        y0 += __shfl_xor_sync(0xffffffffu, y0, o);
        y1 += __shfl_xor_sync(0xffffffffu, y1, o);
    }
    if (lane == 0) {
        out[i * 2]     = y0 + bias[i * 2];
        out[i * 2 + 1] = y1 + bias[i * 2 + 1];
    }
}

// ---------------- launch ----------------
extern "C" void kernel_launch(void* const* d_in, const int* in_sizes, int n_in,
                              void* d_out, int out_size) {
    const float* fp    = (const float*)d_in[0];
    const float* bp    = (const float*)d_in[1];
    const float* ff    = (const float*)d_in[2];
    const float* bfeat = (const float*)d_in[3];
    const float* sup   = (const float*)d_in[4];
    const int*   fi    = (const int*)d_in[5];
    const int*   fj    = (const int*)d_in[6];
    const int*   bfm   = (const int*)d_in[7];
    const int*   bb    = (const int*)d_in[8];
    const float* W0    = (const float*)d_in[9];
    const float* W1    = (const float*)d_in[10];
    const float* W2    = (const float*)d_in[11];
    const float* W3    = (const float*)d_in[12];
    const float* W4    = (const float*)d_in[13];
    const float* fc0   = (const float*)d_in[14];
    const float* fc1   = (const float*)d_in[15];
    const float* fc2   = (const float*)d_in[16];
    const float* fc3   = (const float*)d_in[17];
    float* out = (float*)d_out;

    float *H, *X1, *X2, *X3, *Yb, *Wt;
    int *cntf, *offf, *curf, *cntb, *offb, *curb;
    EdgeRec *ef, *eb;
    cudaGetSymbolAddress((void**)&H,  g_H);
    cudaGetSymbolAddress((void**)&X1, g_X1);
    cudaGetSymbolAddress((void**)&X2, g_X2);
    cudaGetSymbolAddress((void**)&X3, g_X3);
    cudaGetSymbolAddress((void**)&Yb, g_Yb);
    cudaGetSymbolAddress((void**)&Wt, g_Wt);
    cudaGetSymbolAddress((void**)&cntf, g_cntf);
    cudaGetSymbolAddress((void**)&offf, g_offf);
    cudaGetSymbolAddress((void**)&curf, g_curf);
    cudaGetSymbolAddress((void**)&cntb, g_cntb);
    cudaGetSymbolAddress((void**)&offb, g_offb);
    cudaGetSymbolAddress((void**)&curb, g_curb);
    cudaGetSymbolAddress((void**)&ef, g_ef);
    cudaGetSymbolAddress((void**)&eb, g_eb);

    // CSR build (by target)
    resetCnt<<<64, 256>>>(cntf, cntb);
    histAll<<<(EF + EB) / 256, 256>>>(fi, bfm, cntf, cntb);
    scan2<<<2, 1024>>>(cntf, offf, curf, cntb, offb, curb);
    buildAll<<<(EF + EB) / 256, 256>>>(fi, fj, bfm, bb, fp, bp, sup,
                                       curf, ef, curb, eb);

    // ---- layer 1: X1 = [relu(ff@fc0) | relu(conv W0) | relu(conv W1)] ----
    conv4<<<NF / 8, 256>>>(ef, offf, ff,    W0, ff,              fc0,             X1, 32);
    conv4<<<NF / 8, 256>>>(eb, offb, bfeat, W1, (const float*)0, (const float*)0, X1, 64);

    // ---- layer 2: X2 = relu(conv(X1,W2) + X1@fc1) ----
    transW<<<(96 * 4096) / 256, 256>>>(W2, Wt, 96, 64, 96 * 4096);
    tf32gemm<<<dim3(32, 128), 256>>>(NF, 4096, 96, X1, Wt, H);
    scatter64F<<<NF / 8, 256>>>(ef, offf, H, X1, fc1, 96, (const float*)0, X2);

    // ---- layer 3: X3 = relu(conv(X2,W3) + X2@fc2 + X2) ----
    transW<<<(64 * 4096) / 256, 256>>>(W3, Wt, 64, 64, 64 * 4096);
    tf32gemm<<<dim3(32, 128), 256>>>(NF, 4096, 64, X2, Wt, H);
    scatter64F<<<NF / 8, 256>>>(ef, offf, H, X2, fc2, 64, X2, X3);

    // ---- layer 4: out = conv(X3,W4) + X3@fc3 (no relu) ----
    transW<<<(64 * 64 * 2) / 256, 256>>>(W4, Wt, 64, 2, 64 * 64 * 2);
    tf32gemm<<<dim3(1, 128), 256>>>(NF, 128, 64, X3, Wt, H);
    gemmBias<<<(NF * 2) / 256, 256>>>(X3, fc3, Yb, 64, 2, NF * 2);
    scatter2<<<NF / 8, 256>>>(ef, offf, H, Yb, out);

    (void)in_sizes; (void)n_in; (void)out_size;
}

// round 13
// speedup vs baseline: 1.3284x; 1.3284x over previous
#include <cuda_runtime.h>
#include <cuda_fp16.h>
#include <math.h>

#define NF 16384
#define NB 4096
#define EF 262144
#define EB 65536

struct __align__(16) EdgeRec { int src; float tu; float tv; int cell; };

__device__ __half g_H[(size_t)NF * 4096];  // 128 MB scratch: H = X @ W_all (fp16)
__device__ float g_X1[NF * 96];
__device__ float g_X2[NF * 64];
__device__ float g_X3[NF * 64];
__device__ float g_Yb[NF * 64];
__device__ float g_Wt[96 * 4096];
__device__ int   g_cntf[NF], g_offf[NF + 1], g_curf[NF];
__device__ int   g_cntb[NF], g_offb[NF + 1], g_curb[NF];
__device__ EdgeRec g_ef[EF];
__device__ EdgeRec g_eb[EB];

__device__ __forceinline__ float tf32r(float x) {
    float y;
    asm("cvt.rna.tf32.f32 %0, %1;" : "=f"(y) : "f"(x));
    return y;
}

// ---------------- CSR build ----------------
__global__ void resetCnt(int* a, int* b) {
    int id = blockIdx.x * blockDim.x + threadIdx.x;
    if (id < NF) { a[id] = 0; b[id] = 0; }
}

__global__ void histAll(const int* __restrict__ fi, const int* __restrict__ bfm,
                        int* __restrict__ cf, int* __restrict__ cb) {
    int e = blockIdx.x * blockDim.x + threadIdx.x;
    if (e < EF) atomicAdd(&cf[fi[e]], 1);
    else if (e < EF + EB) atomicAdd(&cb[bfm[e - EF]], 1);
}

// both scans in ONE launch: block 0 -> fluid, block 1 -> boundary
__global__ void scan2(const int* __restrict__ cf, int* __restrict__ of, int* __restrict__ uf,
                      const int* __restrict__ cb, int* __restrict__ ob, int* __restrict__ ub) {
    const int* cnt = blockIdx.x ? cb : cf;
    int* offs = blockIdx.x ? ob : of;
    int* cur  = blockIdx.x ? ub : uf;
    __shared__ int wsum[32];
    int t = threadIdx.x;
    int lane = t & 31, warp = t >> 5;
    int base = t * 16;
    int local[16];
    int sum = 0;
#pragma unroll
    for (int j = 0; j < 16; j++) { local[j] = sum; sum += cnt[base + j]; }
    int inc = sum;
#pragma unroll
    for (int o = 1; o < 32; o <<= 1) {
        int v = __shfl_up_sync(0xffffffffu, inc, o);
        if (lane >= o) inc += v;
    }
    if (lane == 31) wsum[warp] = inc;
    __syncthreads();
    if (warp == 0) {
        int w = wsum[lane];
#pragma unroll
        for (int o = 1; o < 32; o <<= 1) {
            int v = __shfl_up_sync(0xffffffffu, w, o);
            if (lane >= o) w += v;
        }
        wsum[lane] = w;
    }
    __syncthreads();
    int pre = inc - sum + (warp ? wsum[warp - 1] : 0);
#pragma unroll
    for (int j = 0; j < 16; j++) {
        int o = pre + local[j];
        offs[base + j] = o;
        cur[base + j]  = o;
    }
    if (t == 1023) offs[NF] = pre + sum;
}

// Edge direction EXACTLY as the reference computes it, including signed zeros:
//   fluid:    d = -(fp[src] - fp[tgt]) / support
//   boundary: d =  (bp[src] - fp[tgt]) / support
// Self-edges on the fluid path give (-0,-0): arctan2(-0,-0) = -pi (cell v=0).
__global__ void buildAll(const int* __restrict__ fi, const int* __restrict__ fj,
                         const int* __restrict__ bfm, const int* __restrict__ bb,
                         const float* __restrict__ fp, const float* __restrict__ bp,
                         const float* __restrict__ supPtr,
                         int* __restrict__ curf, EdgeRec* __restrict__ ef,
                         int* __restrict__ curb, EdgeRec* __restrict__ eb) {
    int e = blockIdx.x * blockDim.x + threadIdx.x;
    if (e >= EF + EB) return;
    int t, s, negate;
    const float *tp, *sp;
    int* cur;
    EdgeRec* recs;
    if (e < EF) {
        t = fi[e]; s = fj[e]; tp = fp; sp = fp; negate = 1; cur = curf; recs = ef;
    } else {
        int eb2 = e - EF;
        t = bfm[eb2]; s = bb[eb2]; tp = fp; sp = bp; negate = 0; cur = curb; recs = eb;
    }
    float sup = supPtr[0];
    float bx = sp[2 * s]     - tp[2 * t];      // src - tgt
    float by = sp[2 * s + 1] - tp[2 * t + 1];
    if (negate) { bx = -bx; by = -by; }        // exact IEEE negation: +0 -> -0
    float dx = bx / sup;
    float dy = by / sup;
    dx = fminf(fmaxf(dx, -1.f), 1.f);
    dy = fminf(fmaxf(dy, -1.f), 1.f);
    float r = sqrtf(dx * dx + dy * dy + 1e-12f);
    float u = 2.f * r - 1.f;
    float theta;
    if (dx == 0.f && dy == 0.f) {
        theta = (__float_as_int(dx) < 0) ? copysignf(3.14159265358979323846f, dy)
                                         : copysignf(0.f, dy);
    } else {
        theta = atan2f(dy, dx);
    }
    float v = theta / 3.14159265358979323846f;
    EdgeRec rec;
    rec.src  = s;
    rec.tu   = (u + 1.f) * 3.5f;
    rec.tv   = (v + 1.f) * 3.5f;
    rec.cell = 0;
    int pos = atomicAdd(&cur[t], 1);
    recs[pos] = rec;
}

// ---------------- generic weight transpose: Wt[c*(64*cout)+k*cout+o] = W[k,c,o]
__global__ void transW(const float* __restrict__ W, float* __restrict__ Wt,
                       int cin, int cout, int n) {
    int id = blockIdx.x * blockDim.x + threadIdx.x;
    if (id >= n) return;
    int o = id % cout;
    int rest = id / cout;
    int k = rest & 63;
    int c = rest >> 6;
    Wt[id] = W[(k * cin + c) * cout + o];
}

// ---------------- layer-1 conv: cin=4, cout=32, weights in smem --------------
__global__ __launch_bounds__(256) void conv4(const EdgeRec* __restrict__ recs,
                                             const int* __restrict__ offs,
                                             const float* __restrict__ xsrc,
                                             const float* __restrict__ W,   // [64][4][32]
                                             const float* __restrict__ xt,
                                             const float* __restrict__ fc0,
                                             float* __restrict__ dst, int dstOff) {
    __shared__ float Ws[8192];
    __shared__ float F0[128];
    for (int t = threadIdx.x; t < 8192; t += 256) Ws[t] = W[t];
    if (xt && threadIdx.x < 128) F0[threadIdx.x] = fc0[threadIdx.x];
    __syncthreads();
    int i = blockIdx.x * 8 + (threadIdx.x >> 5);
    int lane = threadIdx.x & 31;
    if (i >= NF) return;
    float y = 0.f;
    int pe = offs[i + 1];
    for (int p = offs[i]; p < pe; ++p) {
        int4 rv = *(const int4*)&recs[p];
        float tu = __int_as_float(rv.y), tv = __int_as_float(rv.z);
        int iu = min(max((int)tu, 0), 6);
        int iv = min(max((int)tv, 0), 6);
        float4 x = *(const float4*)&xsrc[rv.x * 4];
#pragma unroll
        for (int du = 0; du <= 1; du++) {
            float wu = fmaxf(0.f, 1.f - fabsf(tu - (float)(iu + du)));
#pragma unroll
            for (int dv = 0; dv <= 1; dv++) {
                float w = wu * fmaxf(0.f, 1.f - fabsf(tv - (float)(iv + dv)));
                const float* ws = &Ws[((iu + du) * 8 + (iv + dv)) * 128];
                y += w * (x.x * ws[lane] + x.y * ws[32 + lane]
                        + x.z * ws[64 + lane] + x.w * ws[96 + lane]);
            }
        }
    }
    dst[i * 96 + dstOff + lane] = fmaxf(y, 0.f);
    if (xt) {
        float4 x = *(const float4*)&xt[i * 4];
        float yl = x.x * F0[lane] + x.y * F0[32 + lane]
                 + x.z * F0[64 + lane] + x.w * F0[96 + lane];
        dst[i * 96 + lane] = fmaxf(yl, 0.f);
    }
}

// generic bias GEMM (layer-4 only)
__global__ void gemmBias(const float* __restrict__ X, const float* __restrict__ F,
                         float* __restrict__ Y, int K, int cout, int total) {
    int id = blockIdx.x * blockDim.x + threadIdx.x;
    if (id >= total) return;
    int i = id / cout, o = id - i * cout;
    const float* x = X + (size_t)i * K;
    float y = 0.f;
#pragma unroll 4
    for (int c = 0; c < K; c++) y += x[c] * F[c * cout + o];
    Y[id] = y;
}

// ---------------- 3xTF32 tensor-core GEMM: C[M,N] = A[M,K] @ B[K,N] ------------
// R9-proven internals (TGBK=16, hi/lo compensation). Epilogue writes fp16.
__device__ __forceinline__ void mma8(float d[4], const unsigned a[4], const unsigned b[2]) {
    asm volatile("mma.sync.aligned.m16n8k8.row.col.f32.tf32.tf32.f32 "
                 "{%0,%1,%2,%3}, {%4,%5,%6,%7}, {%8,%9}, {%0,%1,%2,%3};"
                 : "+f"(d[0]), "+f"(d[1]), "+f"(d[2]), "+f"(d[3])
                 : "r"(a[0]), "r"(a[1]), "r"(a[2]), "r"(a[3]),
                   "r"(b[0]), "r"(b[1]));
}

#define TGBK 16
#define TGPAD 136
__global__ __launch_bounds__(256) void tf32gemm(int M, int N, int K,
                                                const float* __restrict__ A,
                                                const float* __restrict__ B,
                                                __half* __restrict__ C) {
    __shared__ float Ah[TGBK][TGPAD], Al[TGBK][TGPAD];
    __shared__ float Bh[TGBK][TGPAD], Bl[TGBK][TGPAD];
    int tid = threadIdx.x;
    int bm = blockIdx.y * 128, bn = blockIdx.x * 128;
    int w = tid >> 5, lane = tid & 31;
    int wm = (w & 1) * 64, wn = (w >> 1) * 32;
    int r = lane >> 2, c = lane & 3;
    float acc[4][4][4];
#pragma unroll
    for (int mt = 0; mt < 4; mt++)
#pragma unroll
        for (int nt = 0; nt < 4; nt++)
#pragma unroll
            for (int q = 0; q < 4; q++) acc[mt][nt][q] = 0.f;

    int arow = tid >> 1, akq = (tid & 1) * 8;   // A: 128 rows x 16 k
    int bk = tid >> 4,  bnq = (tid & 15) * 8;   // B: 16 k x 128 n

    for (int k0 = 0; k0 < K; k0 += TGBK) {
        {
            const float* ap = A + (size_t)(bm + arow) * K + k0 + akq;
            float4 v0 = *(const float4*)ap;
            float4 v1 = *(const float4*)(ap + 4);
            float v[8] = {v0.x, v0.y, v0.z, v0.w, v1.x, v1.y, v1.z, v1.w};
#pragma unroll
            for (int j = 0; j < 8; j++) {
                float hi = tf32r(v[j]);
                Ah[akq + j][arow] = hi;
                Al[akq + j][arow] = tf32r(v[j] - hi);
            }
        }
        {
            const float* bp = B + (size_t)(k0 + bk) * N + bn + bnq;
            float4 v0 = *(const float4*)bp;
            float4 v1 = *(const float4*)(bp + 4);
            float4 h0 = make_float4(tf32r(v0.x), tf32r(v0.y), tf32r(v0.z), tf32r(v0.w));
            float4 h1 = make_float4(tf32r(v1.x), tf32r(v1.y), tf32r(v1.z), tf32r(v1.w));
            float4 l0 = make_float4(tf32r(v0.x - h0.x), tf32r(v0.y - h0.y),
                                    tf32r(v0.z - h0.z), tf32r(v0.w - h0.w));
            float4 l1 = make_float4(tf32r(v1.x - h1.x), tf32r(v1.y - h1.y),
                                    tf32r(v1.z - h1.z), tf32r(v1.w - h1.w));
            *(float4*)&Bh[bk][bnq]     = h0;
            *(float4*)&Bh[bk][bnq + 4] = h1;
            *(float4*)&Bl[bk][bnq]     = l0;
            *(float4*)&Bl[bk][bnq + 4] = l1;
        }
        __syncthreads();

#pragma unroll
        for (int ks = 0; ks < TGBK; ks += 8) {
            unsigned afh[4][4], bfh[4][2];
#pragma unroll
            for (int mt = 0; mt < 4; mt++) {
                int m = wm + mt * 16 + r;
                afh[mt][0] = __float_as_uint(Ah[ks + c][m]);
                afh[mt][1] = __float_as_uint(Ah[ks + c][m + 8]);
                afh[mt][2] = __float_as_uint(Ah[ks + c + 4][m]);
                afh[mt][3] = __float_as_uint(Ah[ks + c + 4][m + 8]);
            }
#pragma unroll
            for (int nt = 0; nt < 4; nt++) {
                int n = wn + nt * 8 + r;
                bfh[nt][0] = __float_as_uint(Bh[ks + c][n]);
                bfh[nt][1] = __float_as_uint(Bh[ks + c + 4][n]);
            }
#pragma unroll
            for (int mt = 0; mt < 4; mt++)
#pragma unroll
                for (int nt = 0; nt < 4; nt++) mma8(acc[mt][nt], afh[mt], bfh[nt]);
            {
                unsigned afl[4][4];
#pragma unroll
                for (int mt = 0; mt < 4; mt++) {
                    int m = wm + mt * 16 + r;
                    afl[mt][0] = __float_as_uint(Al[ks + c][m]);
                    afl[mt][1] = __float_as_uint(Al[ks + c][m + 8]);
                    afl[mt][2] = __float_as_uint(Al[ks + c + 4][m]);
                    afl[mt][3] = __float_as_uint(Al[ks + c + 4][m + 8]);
                }
#pragma unroll
                for (int mt = 0; mt < 4; mt++)
#pragma unroll
                    for (int nt = 0; nt < 4; nt++) mma8(acc[mt][nt], afl[mt], bfh[nt]);
            }
            {
                unsigned bfl[4][2];
#pragma unroll
                for (int nt = 0; nt < 4; nt++) {
                    int n = wn + nt * 8 + r;
                    bfl[nt][0] = __float_as_uint(Bl[ks + c][n]);
                    bfl[nt][1] = __float_as_uint(Bl[ks + c + 4][n]);
                }
#pragma unroll
                for (int mt = 0; mt < 4; mt++)
#pragma unroll
                    for (int nt = 0; nt < 4; nt++) mma8(acc[mt][nt], afh[mt], bfl[nt]);
            }
        }
        __syncthreads();
    }
#pragma unroll
    for (int mt = 0; mt < 4; mt++)
#pragma unroll
        for (int nt = 0; nt < 4; nt++) {
            int m0 = bm + wm + mt * 16 + r;
            int n0 = bn + wn + nt * 8 + 2 * c;
            *(__half2*)(C + (size_t)m0 * N + n0) =
                __floats2half2_rn(acc[mt][nt][0], acc[mt][nt][1]);
            *(__half2*)(C + (size_t)(m0 + 8) * N + n0) =
                __floats2half2_rn(acc[mt][nt][2], acc[mt][nt][3]);
        }
}

// ---------------- scatter for COUT=64 (fp16 H) with FUSED bias GEMM ------------
// lane handles channels (2*lane, 2*lane+1) -> one aligned half2 per corner.
__global__ __launch_bounds__(256) void scatter64F(const EdgeRec* __restrict__ recs,
                                                  const int* __restrict__ offs,
                                                  const __half* __restrict__ H,
                                                  const float* __restrict__ Xb,
                                                  const float* __restrict__ F, int KB,
                                                  const float* __restrict__ resid,
                                                  float* __restrict__ out) {
    __shared__ float Fs[96 * 64];
    for (int t = threadIdx.x; t < KB * 64; t += 256) Fs[t] = F[t];
    __syncthreads();
    int i = blockIdx.x * 8 + (threadIdx.x >> 5);
    int lane = threadIdx.x & 31;
    if (i >= NF) return;
    int c2 = 2 * lane;
    float y0 = 0.f, y1 = 0.f;
    int pe = offs[i + 1];
#pragma unroll 2
    for (int p = offs[i]; p < pe; ++p) {
        int4 rv = *(const int4*)&recs[p];
        float tu = __int_as_float(rv.y), tv = __int_as_float(rv.z);
        int iu = min(max((int)tu, 0), 6);
        int iv = min(max((int)tv, 0), 6);
        const __half* hb = H + (size_t)rv.x * 4096 + c2;
#pragma unroll
        for (int du = 0; du <= 1; du++) {
            float wu = fmaxf(0.f, 1.f - fabsf(tu - (float)(iu + du)));
#pragma unroll
            for (int dv = 0; dv <= 1; dv++) {
                float w = wu * fmaxf(0.f, 1.f - fabsf(tv - (float)(iv + dv)));
                float2 f = __half22float2(
                    *(const __half2*)(hb + ((iu + du) * 8 + (iv + dv)) * 64));
                y0 += w * f.x;
                y1 += w * f.y;
            }
        }
    }
    const float* x = Xb + (size_t)i * KB;
    for (int cc = 0; cc < KB; cc++) {
        float xv = x[cc];
        y0 += xv * Fs[cc * 64 + c2];
        y1 += xv * Fs[cc * 64 + c2 + 1];
    }
    if (resid) { y0 += resid[i * 64 + c2]; y1 += resid[i * 64 + c2 + 1]; }
    out[i * 64 + c2]     = fmaxf(y0, 0.f);
    out[i * 64 + c2 + 1] = fmaxf(y1, 0.f);
}

// ---------------- scatter for COUT=2 (fp16 H), precomputed bias, no relu -------
__global__ __launch_bounds__(256) void scatter2(const EdgeRec* __restrict__ recs,
                                                const int* __restrict__ offs,
                                                const __half* __restrict__ H,
                                                const float* __restrict__ bias,
                                                float* __restrict__ out) {
    int i = blockIdx.x * 8 + (threadIdx.x >> 5);
    int lane = threadIdx.x & 31;
    if (i >= NF) return;
    float y0 = 0.f, y1 = 0.f;
    int pe = offs[i + 1];
    for (int p = offs[i] + lane; p < pe; p += 32) {
        int4 rv = *(const int4*)&recs[p];
        float tu = __int_as_float(rv.y), tv = __int_as_float(rv.z);
        int iu = min(max((int)tu, 0), 6);
        int iv = min(max((int)tv, 0), 6);
        const __half* hb = H + (size_t)rv.x * 128;
#pragma unroll
        for (int du = 0; du <= 1; du++) {
            float wu = fmaxf(0.f, 1.f - fabsf(tu - (float)(iu + du)));
#pragma unroll
            for (int dv = 0; dv <= 1; dv++) {
                float w = wu * fmaxf(0.f, 1.f - fabsf(tv - (float)(iv + dv)));
                float2 f = __half22float2(
                    *(const __half2*)(hb + ((iu + du) * 8 + (iv + dv)) * 2));
                y0 += w * f.x;
                y1 += w * f.y;
            }
        }
    }
#pragma unroll
    for (int o = 16; o > 0; o >>= 1) {
        y0 += __shfl_xor_sync(0xffffffffu, y0, o);
        y1 += __shfl_xor_sync(0xffffffffu, y1, o);
    }
    if (lane == 0) {
        out[i * 2]     = y0 + bias[i * 2];
        out[i * 2 + 1] = y1 + bias[i * 2 + 1];
    }
}

// ---------------- launch ----------------
extern "C" void kernel_launch(void* const* d_in, const int* in_sizes, int n_in,
                              void* d_out, int out_size) {
    const float* fp    = (const float*)d_in[0];
    const float* bp    = (const float*)d_in[1];
    const float* ff    = (const float*)d_in[2];
    const float* bfeat = (const float*)d_in[3];
    const float* sup   = (const float*)d_in[4];
    const int*   fi    = (const int*)d_in[5];
    const int*   fj    = (const int*)d_in[6];
    const int*   bfm   = (const int*)d_in[7];
    const int*   bb    = (const int*)d_in[8];
    const float* W0    = (const float*)d_in[9];
    const float* W1    = (const float*)d_in[10];
    const float* W2    = (const float*)d_in[11];
    const float* W3    = (const float*)d_in[12];
    const float* W4    = (const float*)d_in[13];
    const float* fc0   = (const float*)d_in[14];
    const float* fc1   = (const float*)d_in[15];
    const float* fc2   = (const float*)d_in[16];
    const float* fc3   = (const float*)d_in[17];
    float* out = (float*)d_out;

    __half* H;
    float *X1, *X2, *X3, *Yb, *Wt;
    int *cntf, *offf, *curf, *cntb, *offb, *curb;
    EdgeRec *ef, *eb;
    cudaGetSymbolAddress((void**)&H,  g_H);
    cudaGetSymbolAddress((void**)&X1, g_X1);
    cudaGetSymbolAddress((void**)&X2, g_X2);
    cudaGetSymbolAddress((void**)&X3, g_X3);
    cudaGetSymbolAddress((void**)&Yb, g_Yb);
    cudaGetSymbolAddress((void**)&Wt, g_Wt);
    cudaGetSymbolAddress((void**)&cntf, g_cntf);
    cudaGetSymbolAddress((void**)&offf, g_offf);
    cudaGetSymbolAddress((void**)&curf, g_curf);
    cudaGetSymbolAddress((void**)&cntb, g_cntb);
    cudaGetSymbolAddress((void**)&offb, g_offb);
    cudaGetSymbolAddress((void**)&curb, g_curb);
    cudaGetSymbolAddress((void**)&ef, g_ef);
    cudaGetSymbolAddress((void**)&eb, g_eb);

    // CSR build (by target)
    resetCnt<<<64, 256>>>(cntf, cntb);
    histAll<<<(EF + EB) / 256, 256>>>(fi, bfm, cntf, cntb);
    scan2<<<2, 1024>>>(cntf, offf, curf, cntb, offb, curb);
    buildAll<<<(EF + EB) / 256, 256>>>(fi, fj, bfm, bb, fp, bp, sup,
                                       curf, ef, curb, eb);

    // ---- layer 1: X1 = [relu(ff@fc0) | relu(conv W0) | relu(conv W1)] ----
    conv4<<<NF / 8, 256>>>(ef, offf, ff,    W0, ff,              fc0,             X1, 32);
    conv4<<<NF / 8, 256>>>(eb, offb, bfeat, W1, (const float*)0, (const float*)0, X1, 64);

    // ---- layer 2: X2 = relu(conv(X1,W2) + X1@fc1) ----
    transW<<<(96 * 4096) / 256, 256>>>(W2, Wt, 96, 64, 96 * 4096);
    tf32gemm<<<dim3(32, 128), 256>>>(NF, 4096, 96, X1, Wt, H);
    scatter64F<<<NF / 8, 256>>>(ef, offf, H, X1, fc1, 96, (const float*)0, X2);

    // ---- layer 3: X3 = relu(conv(X2,W3) + X2@fc2 + X2) ----
    transW<<<(64 * 4096) / 256, 256>>>(W3, Wt, 64, 64, 64 * 4096);
    tf32gemm<<<dim3(32, 128), 256>>>(NF, 4096, 64, X2, Wt, H);
    scatter64F<<<NF / 8, 256>>>(ef, offf, H, X2, fc2, 64, X2, X3);

    // ---- layer 4: out = conv(X3,W4) + X3@fc3 (no relu) ----
    transW<<<(64 * 64 * 2) / 256, 256>>>(W4, Wt, 64, 2, 64 * 64 * 2);
    tf32gemm<<<dim3(1, 128), 256>>>(NF, 128, 64, X3, Wt, H);
    gemmBias<<<(NF * 2) / 256, 256>>>(X3, fc3, Yb, 64, 2, NF * 2);
    scatter2<<<NF / 8, 256>>>(ef, offf, H, Yb, out);

    (void)in_sizes; (void)n_in; (void)out_size;
}

// round 14
// speedup vs baseline: 1.6182x; 1.2181x over previous
#include <cuda_runtime.h>
#include <cuda_fp16.h>
#include <math.h>

#define NF 16384
#define NB 4096
#define EF 262144
#define EB 65536

struct __align__(16) EdgeRec { int src; float tu; float tv; int cell; };

__device__ __half g_H[(size_t)NF * 4096];  // 128 MB scratch: H = X @ W_all (fp16)
__device__ float g_X1[NF * 96];
__device__ float g_X2[NF * 64];
__device__ float g_X3[NF * 64];
__device__ float g_Yb[NF * 64];
__device__ __half g_Wh[4096 * 96];         // weights, fp16 hi, [n][K] transposed
__device__ __half g_Wl[4096 * 96];         // weights, fp16 lo residual
__device__ int   g_cntf[NF], g_offf[NF + 1], g_curf[NF];
__device__ int   g_cntb[NF], g_offb[NF + 1], g_curb[NF];
__device__ EdgeRec g_ef[EF];
__device__ EdgeRec g_eb[EB];

// ---------------- CSR build ----------------
__global__ void resetCnt(int* a, int* b) {
    int id = blockIdx.x * blockDim.x + threadIdx.x;
    if (id < NF) { a[id] = 0; b[id] = 0; }
}

__global__ void histAll(const int* __restrict__ fi, const int* __restrict__ bfm,
                        int* __restrict__ cf, int* __restrict__ cb) {
    int e = blockIdx.x * blockDim.x + threadIdx.x;
    if (e < EF) atomicAdd(&cf[fi[e]], 1);
    else if (e < EF + EB) atomicAdd(&cb[bfm[e - EF]], 1);
}

// both scans in ONE launch: block 0 -> fluid, block 1 -> boundary
__global__ void scan2(const int* __restrict__ cf, int* __restrict__ of, int* __restrict__ uf,
                      const int* __restrict__ cb, int* __restrict__ ob, int* __restrict__ ub) {
    const int* cnt = blockIdx.x ? cb : cf;
    int* offs = blockIdx.x ? ob : of;
    int* cur  = blockIdx.x ? ub : uf;
    __shared__ int wsum[32];
    int t = threadIdx.x;
    int lane = t & 31, warp = t >> 5;
    int base = t * 16;
    int local[16];
    int sum = 0;
#pragma unroll
    for (int j = 0; j < 16; j++) { local[j] = sum; sum += cnt[base + j]; }
    int inc = sum;
#pragma unroll
    for (int o = 1; o < 32; o <<= 1) {
        int v = __shfl_up_sync(0xffffffffu, inc, o);
        if (lane >= o) inc += v;
    }
    if (lane == 31) wsum[warp] = inc;
    __syncthreads();
    if (warp == 0) {
        int w = wsum[lane];
#pragma unroll
        for (int o = 1; o < 32; o <<= 1) {
            int v = __shfl_up_sync(0xffffffffu, w, o);
            if (lane >= o) w += v;
        }
        wsum[lane] = w;
    }
    __syncthreads();
    int pre = inc - sum + (warp ? wsum[warp - 1] : 0);
#pragma unroll
    for (int j = 0; j < 16; j++) {
        int o = pre + local[j];
        offs[base + j] = o;
        cur[base + j]  = o;
    }
    if (t == 1023) offs[NF] = pre + sum;
}

// Edge direction EXACTLY as the reference computes it, including signed zeros:
//   fluid:    d = -(fp[src] - fp[tgt]) / support
//   boundary: d =  (bp[src] - fp[tgt]) / support
// Self-edges on the fluid path give (-0,-0): arctan2(-0,-0) = -pi (cell v=0).
__global__ void buildAll(const int* __restrict__ fi, const int* __restrict__ fj,
                         const int* __restrict__ bfm, const int* __restrict__ bb,
                         const float* __restrict__ fp, const float* __restrict__ bp,
                         const float* __restrict__ supPtr,
                         int* __restrict__ curf, EdgeRec* __restrict__ ef,
                         int* __restrict__ curb, EdgeRec* __restrict__ eb) {
    int e = blockIdx.x * blockDim.x + threadIdx.x;
    if (e >= EF + EB) return;
    int t, s, negate;
    const float *tp, *sp;
    int* cur;
    EdgeRec* recs;
    if (e < EF) {
        t = fi[e]; s = fj[e]; tp = fp; sp = fp; negate = 1; cur = curf; recs = ef;
    } else {
        int eb2 = e - EF;
        t = bfm[eb2]; s = bb[eb2]; tp = fp; sp = bp; negate = 0; cur = curb; recs = eb;
    }
    float sup = supPtr[0];
    float bx = sp[2 * s]     - tp[2 * t];      // src - tgt
    float by = sp[2 * s + 1] - tp[2 * t + 1];
    if (negate) { bx = -bx; by = -by; }        // exact IEEE negation: +0 -> -0
    float dx = bx / sup;
    float dy = by / sup;
    dx = fminf(fmaxf(dx, -1.f), 1.f);
    dy = fminf(fmaxf(dy, -1.f), 1.f);
    float r = sqrtf(dx * dx + dy * dy + 1e-12f);
    float u = 2.f * r - 1.f;
    float theta;
    if (dx == 0.f && dy == 0.f) {
        theta = (__float_as_int(dx) < 0) ? copysignf(3.14159265358979323846f, dy)
                                         : copysignf(0.f, dy);
    } else {
        theta = atan2f(dy, dx);
    }
    float v = theta / 3.14159265358979323846f;
    EdgeRec rec;
    rec.src  = s;
    rec.tu   = (u + 1.f) * 3.5f;
    rec.tv   = (v + 1.f) * 3.5f;
    rec.cell = 0;
    int pos = atomicAdd(&cur[t], 1);
    recs[pos] = rec;
}

// ---- weight transpose + fp16 hi/lo split: BT[n][c] = W[k,c,o], n = k*cout+o ---
__global__ void transWh(const float* __restrict__ W, __half* __restrict__ Bh,
                        __half* __restrict__ Bl, int cin, int cout, int n) {
    int id = blockIdx.x * blockDim.x + threadIdx.x;
    if (id >= n) return;
    int c = id % cin;
    int nIdx = id / cin;
    int o = nIdx % cout;
    int k = nIdx / cout;
    float x = W[(k * cin + c) * cout + o];
    __half h = __float2half_rn(x);
    Bh[id] = h;
    Bl[id] = __float2half_rn(x - __half2float(h));
}

// ---------------- layer-1 conv: cin=4, cout=32, weights in smem --------------
__global__ __launch_bounds__(256) void conv4(const EdgeRec* __restrict__ recs,
                                             const int* __restrict__ offs,
                                             const float* __restrict__ xsrc,
                                             const float* __restrict__ W,   // [64][4][32]
                                             const float* __restrict__ xt,
                                             const float* __restrict__ fc0,
                                             float* __restrict__ dst, int dstOff) {
    __shared__ float Ws[8192];
    __shared__ float F0[128];
    for (int t = threadIdx.x; t < 8192; t += 256) Ws[t] = W[t];
    if (xt && threadIdx.x < 128) F0[threadIdx.x] = fc0[threadIdx.x];
    __syncthreads();
    int i = blockIdx.x * 8 + (threadIdx.x >> 5);
    int lane = threadIdx.x & 31;
    if (i >= NF) return;
    float y = 0.f;
    int pe = offs[i + 1];
    for (int p = offs[i]; p < pe; ++p) {
        int4 rv = *(const int4*)&recs[p];
        float tu = __int_as_float(rv.y), tv = __int_as_float(rv.z);
        int iu = min(max((int)tu, 0), 6);
        int iv = min(max((int)tv, 0), 6);
        float4 x = *(const float4*)&xsrc[rv.x * 4];
#pragma unroll
        for (int du = 0; du <= 1; du++) {
            float wu = fmaxf(0.f, 1.f - fabsf(tu - (float)(iu + du)));
#pragma unroll
            for (int dv = 0; dv <= 1; dv++) {
                float w = wu * fmaxf(0.f, 1.f - fabsf(tv - (float)(iv + dv)));
                const float* ws = &Ws[((iu + du) * 8 + (iv + dv)) * 128];
                y += w * (x.x * ws[lane] + x.y * ws[32 + lane]
                        + x.z * ws[64 + lane] + x.w * ws[96 + lane]);
            }
        }
    }
    dst[i * 96 + dstOff + lane] = fmaxf(y, 0.f);
    if (xt) {
        float4 x = *(const float4*)&xt[i * 4];
        float yl = x.x * F0[lane] + x.y * F0[32 + lane]
                 + x.z * F0[64 + lane] + x.w * F0[96 + lane];
        dst[i * 96 + lane] = fmaxf(yl, 0.f);
    }
}

// generic bias GEMM (layer-4 only, exact fp32)
__global__ void gemmBias(const float* __restrict__ X, const float* __restrict__ F,
                         float* __restrict__ Y, int K, int cout, int total) {
    int id = blockIdx.x * blockDim.x + threadIdx.x;
    if (id >= total) return;
    int i = id / cout, o = id - i * cout;
    const float* x = X + (size_t)i * K;
    float y = 0.f;
#pragma unroll 4
    for (int c = 0; c < K; c++) y += x[c] * F[c * cout + o];
    Y[id] = y;
}

// ---------------- 3-pass fp16 tensor-core GEMM: C = A @ B^T' ------------------
// A fp32 [M][K] split hi/lo at staging; B pre-split fp16 [N][K] (transposed).
// C = AhBh + AlBh + AhBl; fp32 accumulate; error ~2^-22 (fp32-equivalent).
// Block 128x128, 8 warps of 64x32, mma m16n8k16. K%16==0.
__device__ __forceinline__ void mma16(float d[4], const unsigned a[4], const unsigned b[2]) {
    asm volatile("mma.sync.aligned.m16n8k16.row.col.f32.f16.f16.f32 "
                 "{%0,%1,%2,%3}, {%4,%5,%6,%7}, {%8,%9}, {%0,%1,%2,%3};"
                 : "+f"(d[0]), "+f"(d[1]), "+f"(d[2]), "+f"(d[3])
                 : "r"(a[0]), "r"(a[1]), "r"(a[2]), "r"(a[3]),
                   "r"(b[0]), "r"(b[1]));
}

#define HSTR 24   // smem row stride in halves (48B): bank = row*12+c, conflict-free
__global__ __launch_bounds__(256) void fp16gemm(int M, int N, int K,
                                                const float* __restrict__ A,
                                                const __half* __restrict__ Bhg,
                                                const __half* __restrict__ Blg,
                                                __half* __restrict__ C) {
    __shared__ __half Ah[128][HSTR], Al[128][HSTR];
    __shared__ __half Bh[128][HSTR], Bl[128][HSTR];
    int tid = threadIdx.x;
    int bm = blockIdx.y * 128, bn = blockIdx.x * 128;
    int w = tid >> 5, lane = tid & 31;
    int wm = (w & 1) * 64, wn = (w >> 1) * 32;
    int r = lane >> 2, c = lane & 3;
    float acc[4][4][4];
#pragma unroll
    for (int mt = 0; mt < 4; mt++)
#pragma unroll
        for (int nt = 0; nt < 4; nt++)
#pragma unroll
            for (int q = 0; q < 4; q++) acc[mt][nt][q] = 0.f;

    int sm = tid >> 1, sko = (tid & 1) * 8;   // 128 rows x 16 k, 8 halves/thread

    for (int k0 = 0; k0 < K; k0 += 16) {
        // stage A row-major [m][k] with fp16 hi/lo split
        {
            const float* ap = A + (size_t)(bm + sm) * K + k0 + sko;
            float4 v0 = *(const float4*)ap;
            float4 v1 = *(const float4*)(ap + 4);
            float vv[8] = {v0.x, v0.y, v0.z, v0.w, v1.x, v1.y, v1.z, v1.w};
#pragma unroll
            for (int j = 0; j < 4; j++) {
                __half h0 = __float2half_rn(vv[2 * j]);
                __half h1 = __float2half_rn(vv[2 * j + 1]);
                *(__half2*)&Ah[sm][sko + 2 * j] = __halves2half2(h0, h1);
                *(__half2*)&Al[sm][sko + 2 * j] = __halves2half2(
                    __float2half_rn(vv[2 * j]     - __half2float(h0)),
                    __float2half_rn(vv[2 * j + 1] - __half2float(h1)));
            }
        }
        // stage B [n][k]: raw 16-byte copies (pre-split in global)
        {
            size_t off = (size_t)(bn + sm) * K + k0 + sko;
            *(uint4*)&Bh[sm][sko] = *(const uint4*)(Bhg + off);
            *(uint4*)&Bl[sm][sko] = *(const uint4*)(Blg + off);
        }
        __syncthreads();

        unsigned ah[4][4], bh[4][2];
#pragma unroll
        for (int mt = 0; mt < 4; mt++) {
            int m = wm + mt * 16 + r;
            ah[mt][0] = *(const unsigned*)&Ah[m][2 * c];
            ah[mt][1] = *(const unsigned*)&Ah[m + 8][2 * c];
            ah[mt][2] = *(const unsigned*)&Ah[m][2 * c + 8];
            ah[mt][3] = *(const unsigned*)&Ah[m + 8][2 * c + 8];
        }
#pragma unroll
        for (int nt = 0; nt < 4; nt++) {
            int n = wn + nt * 8 + r;
            bh[nt][0] = *(const unsigned*)&Bh[n][2 * c];
            bh[nt][1] = *(const unsigned*)&Bh[n][2 * c + 8];
        }
#pragma unroll
        for (int mt = 0; mt < 4; mt++)
#pragma unroll
            for (int nt = 0; nt < 4; nt++) mma16(acc[mt][nt], ah[mt], bh[nt]);
        // lo(A) * hi(B)
        {
            unsigned al[4][4];
#pragma unroll
            for (int mt = 0; mt < 4; mt++) {
                int m = wm + mt * 16 + r;
                al[mt][0] = *(const unsigned*)&Al[m][2 * c];
                al[mt][1] = *(const unsigned*)&Al[m + 8][2 * c];
                al[mt][2] = *(const unsigned*)&Al[m][2 * c + 8];
                al[mt][3] = *(const unsigned*)&Al[m + 8][2 * c + 8];
            }
#pragma unroll
            for (int mt = 0; mt < 4; mt++)
#pragma unroll
                for (int nt = 0; nt < 4; nt++) mma16(acc[mt][nt], al[mt], bh[nt]);
        }
        // hi(A) * lo(B)
        {
            unsigned bl[4][2];
#pragma unroll
            for (int nt = 0; nt < 4; nt++) {
                int n = wn + nt * 8 + r;
                bl[nt][0] = *(const unsigned*)&Bl[n][2 * c];
                bl[nt][1] = *(const unsigned*)&Bl[n][2 * c + 8];
            }
#pragma unroll
            for (int mt = 0; mt < 4; mt++)
#pragma unroll
                for (int nt = 0; nt < 4; nt++) mma16(acc[mt][nt], ah[mt], bl[nt]);
        }
        __syncthreads();
    }
#pragma unroll
    for (int mt = 0; mt < 4; mt++)
#pragma unroll
        for (int nt = 0; nt < 4; nt++) {
            int m0 = bm + wm + mt * 16 + r;
            int n0 = bn + wn + nt * 8 + 2 * c;
            *(__half2*)(C + (size_t)m0 * N + n0) =
                __floats2half2_rn(acc[mt][nt][0], acc[mt][nt][1]);
            *(__half2*)(C + (size_t)(m0 + 8) * N + n0) =
                __floats2half2_rn(acc[mt][nt][2], acc[mt][nt][3]);
        }
}

// ---------------- scatter for COUT=64 (fp16 H) with FUSED bias GEMM ------------
__global__ __launch_bounds__(256) void scatter64F(const EdgeRec* __restrict__ recs,
                                                  const int* __restrict__ offs,
                                                  const __half* __restrict__ H,
                                                  const float* __restrict__ Xb,
                                                  const float* __restrict__ F, int KB,
                                                  const float* __restrict__ resid,
                                                  float* __restrict__ out) {
    __shared__ float Fs[96 * 64];
    for (int t = threadIdx.x; t < KB * 64; t += 256) Fs[t] = F[t];
    __syncthreads();
    int i = blockIdx.x * 8 + (threadIdx.x >> 5);
    int lane = threadIdx.x & 31;
    if (i >= NF) return;
    int c2 = 2 * lane;
    float y0 = 0.f, y1 = 0.f;
    int pe = offs[i + 1];
#pragma unroll 2
    for (int p = offs[i]; p < pe; ++p) {
        int4 rv = *(const int4*)&recs[p];
        float tu = __int_as_float(rv.y), tv = __int_as_float(rv.z);
        int iu = min(max((int)tu, 0), 6);
        int iv = min(max((int)tv, 0), 6);
        const __half* hb = H + (size_t)rv.x * 4096 + c2;
#pragma unroll
        for (int du = 0; du <= 1; du++) {
            float wu = fmaxf(0.f, 1.f - fabsf(tu - (float)(iu + du)));
#pragma unroll
            for (int dv = 0; dv <= 1; dv++) {
                float w = wu * fmaxf(0.f, 1.f - fabsf(tv - (float)(iv + dv)));
                float2 f = __half22float2(
                    *(const __half2*)(hb + ((iu + du) * 8 + (iv + dv)) * 64));
                y0 += w * f.x;
                y1 += w * f.y;
            }
        }
    }
    const float* x = Xb + (size_t)i * KB;
    for (int cc = 0; cc < KB; cc++) {
        float xv = x[cc];
        y0 += xv * Fs[cc * 64 + c2];
        y1 += xv * Fs[cc * 64 + c2 + 1];
    }
    if (resid) { y0 += resid[i * 64 + c2]; y1 += resid[i * 64 + c2 + 1]; }
    out[i * 64 + c2]     = fmaxf(y0, 0.f);
    out[i * 64 + c2 + 1] = fmaxf(y1, 0.f);
}

// ---------------- scatter for COUT=2 (fp16 H), precomputed bias, no relu -------
__global__ __launch_bounds__(256) void scatter2(const EdgeRec* __restrict__ recs,
                                                const int* __restrict__ offs,
                                                const __half* __restrict__ H,
                                                const float* __restrict__ bias,
                                                float* __restrict__ out) {
    int i = blockIdx.x * 8 + (threadIdx.x >> 5);
    int lane = threadIdx.x & 31;
    if (i >= NF) return;
    float y0 = 0.f, y1 = 0.f;
    int pe = offs[i + 1];
    for (int p = offs[i] + lane; p < pe; p += 32) {
        int4 rv = *(const int4*)&recs[p];
        float tu = __int_as_float(rv.y), tv = __int_as_float(rv.z);
        int iu = min(max((int)tu, 0), 6);
        int iv = min(max((int)tv, 0), 6);
        const __half* hb = H + (size_t)rv.x * 128;
#pragma unroll
        for (int du = 0; du <= 1; du++) {
            float wu = fmaxf(0.f, 1.f - fabsf(tu - (float)(iu + du)));
#pragma unroll
            for (int dv = 0; dv <= 1; dv++) {
                float w = wu * fmaxf(0.f, 1.f - fabsf(tv - (float)(iv + dv)));
                float2 f = __half22float2(
                    *(const __half2*)(hb + ((iu + du) * 8 + (iv + dv)) * 2));
                y0 += w * f.x;
                y1 += w * f.y;
            }
        }
    }
#pragma unroll
    for (int o = 16; o > 0; o >>= 1) {
        y0 += __shfl_xor_sync(0xffffffffu, y0, o);
        y1 += __shfl_xor_sync(0xffffffffu, y1, o);
    }
    if (lane == 0) {
        out[i * 2]     = y0 + bias[i * 2];
        out[i * 2 + 1] = y1 + bias[i * 2 + 1];
    }
}

// ---------------- launch ----------------
extern "C" void kernel_launch(void* const* d_in, const int* in_sizes, int n_in,
                              void* d_out, int out_size) {
    const float* fp    = (const float*)d_in[0];
    const float* bp    = (const float*)d_in[1];
    const float* ff    = (const float*)d_in[2];
    const float* bfeat = (const float*)d_in[3];
    const float* sup   = (const float*)d_in[4];
    const int*   fi    = (const int*)d_in[5];
    const int*   fj    = (const int*)d_in[6];
    const int*   bfm   = (const int*)d_in[7];
    const int*   bb    = (const int*)d_in[8];
    const float* W0    = (const float*)d_in[9];
    const float* W1    = (const float*)d_in[10];
    const float* W2    = (const float*)d_in[11];
    const float* W3    = (const float*)d_in[12];
    const float* W4    = (const float*)d_in[13];
    const float* fc0   = (const float*)d_in[14];
    const float* fc1   = (const float*)d_in[15];
    const float* fc2   = (const float*)d_in[16];
    const float* fc3   = (const float*)d_in[17];
    float* out = (float*)d_out;

    __half *H, *Wh, *Wl;
    float *X1, *X2, *X3, *Yb;
    int *cntf, *offf, *curf, *cntb, *offb, *curb;
    EdgeRec *ef, *eb;
    cudaGetSymbolAddress((void**)&H,  g_H);
    cudaGetSymbolAddress((void**)&Wh, g_Wh);
    cudaGetSymbolAddress((void**)&Wl, g_Wl);
    cudaGetSymbolAddress((void**)&X1, g_X1);
    cudaGetSymbolAddress((void**)&X2, g_X2);
    cudaGetSymbolAddress((void**)&X3, g_X3);
    cudaGetSymbolAddress((void**)&Yb, g_Yb);
    cudaGetSymbolAddress((void**)&cntf, g_cntf);
    cudaGetSymbolAddress((void**)&offf, g_offf);
    cudaGetSymbolAddress((void**)&curf, g_curf);
    cudaGetSymbolAddress((void**)&cntb, g_cntb);
    cudaGetSymbolAddress((void**)&offb, g_offb);
    cudaGetSymbolAddress((void**)&curb, g_curb);
    cudaGetSymbolAddress((void**)&ef, g_ef);
    cudaGetSymbolAddress((void**)&eb, g_eb);

    // CSR build (by target)
    resetCnt<<<64, 256>>>(cntf, cntb);
    histAll<<<(EF + EB) / 256, 256>>>(fi, bfm, cntf, cntb);
    scan2<<<2, 1024>>>(cntf, offf, curf, cntb, offb, curb);
    buildAll<<<(EF + EB) / 256, 256>>>(fi, fj, bfm, bb, fp, bp, sup,
                                       curf, ef, curb, eb);

    // ---- layer 1: X1 = [relu(ff@fc0) | relu(conv W0) | relu(conv W1)] ----
    conv4<<<NF / 8, 256>>>(ef, offf, ff,    W0, ff,              fc0,             X1, 32);
    conv4<<<NF / 8, 256>>>(eb, offb, bfeat, W1, (const float*)0, (const float*)0, X1, 64);

    // ---- layer 2: X2 = relu(conv(X1,W2) + X1@fc1) ----
    transWh<<<(96 * 4096) / 256, 256>>>(W2, Wh, Wl, 96, 64, 96 * 4096);
    fp16gemm<<<dim3(32, 128), 256>>>(NF, 4096, 96, X1, Wh, Wl, H);
    scatter64F<<<NF / 8, 256>>>(ef, offf, H, X1, fc1, 96, (const float*)0, X2);

    // ---- layer 3: X3 = relu(conv(X2,W3) + X2@fc2 + X2) ----
    transWh<<<(64 * 4096) / 256, 256>>>(W3, Wh, Wl, 64, 64, 64 * 4096);
    fp16gemm<<<dim3(32, 128), 256>>>(NF, 4096, 64, X2, Wh, Wl, H);
    scatter64F<<<NF / 8, 256>>>(ef, offf, H, X2, fc2, 64, X2, X3);

    // ---- layer 4: out = conv(X3,W4) + X3@fc3 (no relu) ----
    transWh<<<(64 * 128) / 256 + 1, 256>>>(W4, Wh, Wl, 64, 2, 64 * 64 * 2);
    fp16gemm<<<dim3(1, 128), 256>>>(NF, 128, 64, X3, Wh, Wl, H);
    gemmBias<<<(NF * 2) / 256, 256>>>(X3, fc3, Yb, 64, 2, NF * 2);
    scatter2<<<NF / 8, 256>>>(ef, offf, H, Yb, out);

    (void)in_sizes; (void)n_in; (void)out_size;
}

// round 15
// speedup vs baseline: 1.8617x; 1.1505x over previous
#include <cuda_runtime.h>
#include <cuda_fp16.h>
#include <math.h>

#define NF 16384
#define NB 4096
#define EF 262144
#define EB 65536

struct __align__(16) EdgeRec { int src; float tu; float tv; int cell; };

__device__ __half g_H[(size_t)NF * 4096];  // 128 MB scratch: H = X @ W_all (fp16)
__device__ float g_X1[NF * 96];
__device__ float g_X2[NF * 64];
__device__ float g_X3[NF * 64];
__device__ float g_Yb[NF * 64];
__device__ __half g_Wh[4096 * 96];         // weights, fp16 hi, [n][K] transposed
__device__ __half g_Wl[4096 * 96];         // weights, fp16 lo residual
__device__ int   g_cntf[NF], g_offf[NF + 1], g_curf[NF];
__device__ int   g_cntb[NF], g_offb[NF + 1], g_curb[NF];
__device__ EdgeRec g_ef[EF];
__device__ EdgeRec g_eb[EB];

// ---------------- CSR build ----------------
__global__ void resetCnt(int* a, int* b) {
    int id = blockIdx.x * blockDim.x + threadIdx.x;
    if (id < NF) { a[id] = 0; b[id] = 0; }
}

__global__ void histAll(const int* __restrict__ fi, const int* __restrict__ bfm,
                        int* __restrict__ cf, int* __restrict__ cb) {
    int e = blockIdx.x * blockDim.x + threadIdx.x;
    if (e < EF) atomicAdd(&cf[fi[e]], 1);
    else if (e < EF + EB) atomicAdd(&cb[bfm[e - EF]], 1);
}

// both scans in ONE launch: block 0 -> fluid, block 1 -> boundary
__global__ void scan2(const int* __restrict__ cf, int* __restrict__ of, int* __restrict__ uf,
                      const int* __restrict__ cb, int* __restrict__ ob, int* __restrict__ ub) {
    const int* cnt = blockIdx.x ? cb : cf;
    int* offs = blockIdx.x ? ob : of;
    int* cur  = blockIdx.x ? ub : uf;
    __shared__ int wsum[32];
    int t = threadIdx.x;
    int lane = t & 31, warp = t >> 5;
    int base = t * 16;
    int local[16];
    int sum = 0;
#pragma unroll
    for (int j = 0; j < 16; j++) { local[j] = sum; sum += cnt[base + j]; }
    int inc = sum;
#pragma unroll
    for (int o = 1; o < 32; o <<= 1) {
        int v = __shfl_up_sync(0xffffffffu, inc, o);
        if (lane >= o) inc += v;
    }
    if (lane == 31) wsum[warp] = inc;
    __syncthreads();
    if (warp == 0) {
        int w = wsum[lane];
#pragma unroll
        for (int o = 1; o < 32; o <<= 1) {
            int v = __shfl_up_sync(0xffffffffu, w, o);
            if (lane >= o) w += v;
        }
        wsum[lane] = w;
    }
    __syncthreads();
    int pre = inc - sum + (warp ? wsum[warp - 1] : 0);
#pragma unroll
    for (int j = 0; j < 16; j++) {
        int o = pre + local[j];
        offs[base + j] = o;
        cur[base + j]  = o;
    }
    if (t == 1023) offs[NF] = pre + sum;
}

// Edge direction EXACTLY as the reference computes it, including signed zeros:
//   fluid:    d = -(fp[src] - fp[tgt]) / support
//   boundary: d =  (bp[src] - fp[tgt]) / support
// Self-edges on the fluid path give (-0,-0): arctan2(-0,-0) = -pi (cell v=0).
__global__ void buildAll(const int* __restrict__ fi, const int* __restrict__ fj,
                         const int* __restrict__ bfm, const int* __restrict__ bb,
                         const float* __restrict__ fp, const float* __restrict__ bp,
                         const float* __restrict__ supPtr,
                         int* __restrict__ curf, EdgeRec* __restrict__ ef,
                         int* __restrict__ curb, EdgeRec* __restrict__ eb) {
    int e = blockIdx.x * blockDim.x + threadIdx.x;
    if (e >= EF + EB) return;
    int t, s, negate;
    const float *tp, *sp;
    int* cur;
    EdgeRec* recs;
    if (e < EF) {
        t = fi[e]; s = fj[e]; tp = fp; sp = fp; negate = 1; cur = curf; recs = ef;
    } else {
        int eb2 = e - EF;
        t = bfm[eb2]; s = bb[eb2]; tp = fp; sp = bp; negate = 0; cur = curb; recs = eb;
    }
    float sup = supPtr[0];
    float bx = sp[2 * s]     - tp[2 * t];      // src - tgt
    float by = sp[2 * s + 1] - tp[2 * t + 1];
    if (negate) { bx = -bx; by = -by; }        // exact IEEE negation: +0 -> -0
    float dx = bx / sup;
    float dy = by / sup;
    dx = fminf(fmaxf(dx, -1.f), 1.f);
    dy = fminf(fmaxf(dy, -1.f), 1.f);
    float r = sqrtf(dx * dx + dy * dy + 1e-12f);
    float u = 2.f * r - 1.f;
    float theta;
    if (dx == 0.f && dy == 0.f) {
        theta = (__float_as_int(dx) < 0) ? copysignf(3.14159265358979323846f, dy)
                                         : copysignf(0.f, dy);
    } else {
        theta = atan2f(dy, dx);
    }
    float v = theta / 3.14159265358979323846f;
    EdgeRec rec;
    rec.src  = s;
    rec.tu   = (u + 1.f) * 3.5f;
    rec.tv   = (v + 1.f) * 3.5f;
    rec.cell = 0;
    int pos = atomicAdd(&cur[t], 1);
    recs[pos] = rec;
}

// ---- weight transpose + fp16 hi/lo split: BT[n][c] = W[k,c,o], n = k*cout+o ---
__global__ void transWh(const float* __restrict__ W, __half* __restrict__ Bh,
                        __half* __restrict__ Bl, int cin, int cout, int n) {
    int id = blockIdx.x * blockDim.x + threadIdx.x;
    if (id >= n) return;
    int c = id % cin;
    int nIdx = id / cin;
    int o = nIdx % cout;
    int k = nIdx / cout;
    float x = W[(k * cin + c) * cout + o];
    __half h = __float2half_rn(x);
    Bh[id] = h;
    Bl[id] = __float2half_rn(x - __half2float(h));
}

// ---------------- layer-1 conv: cin=4, cout=32, weights in smem --------------
__global__ __launch_bounds__(256) void conv4(const EdgeRec* __restrict__ recs,
                                             const int* __restrict__ offs,
                                             const float* __restrict__ xsrc,
                                             const float* __restrict__ W,   // [64][4][32]
                                             const float* __restrict__ xt,
                                             const float* __restrict__ fc0,
                                             float* __restrict__ dst, int dstOff) {
    __shared__ float Ws[8192];
    __shared__ float F0[128];
    for (int t = threadIdx.x; t < 8192; t += 256) Ws[t] = W[t];
    if (xt && threadIdx.x < 128) F0[threadIdx.x] = fc0[threadIdx.x];
    __syncthreads();
    int i = blockIdx.x * 8 + (threadIdx.x >> 5);
    int lane = threadIdx.x & 31;
    if (i >= NF) return;
    float y = 0.f;
    int pe = offs[i + 1];
    for (int p = offs[i]; p < pe; ++p) {
        int4 rv = *(const int4*)&recs[p];
        float tu = __int_as_float(rv.y), tv = __int_as_float(rv.z);
        int iu = min(max((int)tu, 0), 6);
        int iv = min(max((int)tv, 0), 6);
        float4 x = *(const float4*)&xsrc[rv.x * 4];
#pragma unroll
        for (int du = 0; du <= 1; du++) {
            float wu = fmaxf(0.f, 1.f - fabsf(tu - (float)(iu + du)));
#pragma unroll
            for (int dv = 0; dv <= 1; dv++) {
                float w = wu * fmaxf(0.f, 1.f - fabsf(tv - (float)(iv + dv)));
                const float* ws = &Ws[((iu + du) * 8 + (iv + dv)) * 128];
                y += w * (x.x * ws[lane] + x.y * ws[32 + lane]
                        + x.z * ws[64 + lane] + x.w * ws[96 + lane]);
            }
        }
    }
    dst[i * 96 + dstOff + lane] = fmaxf(y, 0.f);
    if (xt) {
        float4 x = *(const float4*)&xt[i * 4];
        float yl = x.x * F0[lane] + x.y * F0[32 + lane]
                 + x.z * F0[64 + lane] + x.w * F0[96 + lane];
        dst[i * 96 + lane] = fmaxf(yl, 0.f);
    }
}

// generic bias GEMM (layer-4 only, exact fp32)
__global__ void gemmBias(const float* __restrict__ X, const float* __restrict__ F,
                         float* __restrict__ Y, int K, int cout, int total) {
    int id = blockIdx.x * blockDim.x + threadIdx.x;
    if (id >= total) return;
    int i = id / cout, o = id - i * cout;
    const float* x = X + (size_t)i * K;
    float y = 0.f;
#pragma unroll 4
    for (int c = 0; c < K; c++) y += x[c] * F[c * cout + o];
    Y[id] = y;
}

// ---------------- 2-pass fp16 tensor-core GEMM: C = Ah @ (Bh + Bl) ------------
// A fp32 [M][K] quantized to fp16 at staging (eps 2^-11, same as tf32 — the R5
// full-tf32 run measured 4.1e-4 total; A-only/2-layer quantization sits below).
// B pre-split fp16 hi/lo [N][K] (weights effectively fp32-exact).
// Block 128x128, 8 warps of 64x32, mma m16n8k16. K%16==0.
__device__ __forceinline__ void mma16(float d[4], const unsigned a[4], const unsigned b[2]) {
    asm volatile("mma.sync.aligned.m16n8k16.row.col.f32.f16.f16.f32 "
                 "{%0,%1,%2,%3}, {%4,%5,%6,%7}, {%8,%9}, {%0,%1,%2,%3};"
                 : "+f"(d[0]), "+f"(d[1]), "+f"(d[2]), "+f"(d[3])
                 : "r"(a[0]), "r"(a[1]), "r"(a[2]), "r"(a[3]),
                   "r"(b[0]), "r"(b[1]));
}

#define HSTR 24   // smem row stride in halves (48B): conflict-free fragment LDS
__global__ __launch_bounds__(256) void fp16gemm(int M, int N, int K,
                                                const float* __restrict__ A,
                                                const __half* __restrict__ Bhg,
                                                const __half* __restrict__ Blg,
                                                __half* __restrict__ C) {
    __shared__ __half Ah[128][HSTR];
    __shared__ __half Bh[128][HSTR], Bl[128][HSTR];
    int tid = threadIdx.x;
    int bm = blockIdx.y * 128, bn = blockIdx.x * 128;
    int w = tid >> 5, lane = tid & 31;
    int wm = (w & 1) * 64, wn = (w >> 1) * 32;
    int r = lane >> 2, c = lane & 3;
    float acc[4][4][4];
#pragma unroll
    for (int mt = 0; mt < 4; mt++)
#pragma unroll
        for (int nt = 0; nt < 4; nt++)
#pragma unroll
            for (int q = 0; q < 4; q++) acc[mt][nt][q] = 0.f;

    int sm = tid >> 1, sko = (tid & 1) * 8;   // 128 rows x 16 k, 8 halves/thread

    for (int k0 = 0; k0 < K; k0 += 16) {
        // stage A row-major [m][k], fp16-quantized
        {
            const float* ap = A + (size_t)(bm + sm) * K + k0 + sko;
            float4 v0 = *(const float4*)ap;
            float4 v1 = *(const float4*)(ap + 4);
            *(__half2*)&Ah[sm][sko]     = __floats2half2_rn(v0.x, v0.y);
            *(__half2*)&Ah[sm][sko + 2] = __floats2half2_rn(v0.z, v0.w);
            *(__half2*)&Ah[sm][sko + 4] = __floats2half2_rn(v1.x, v1.y);
            *(__half2*)&Ah[sm][sko + 6] = __floats2half2_rn(v1.z, v1.w);
        }
        // stage B [n][k]: raw 16-byte copies (pre-split in global)
        {
            size_t off = (size_t)(bn + sm) * K + k0 + sko;
            *(uint4*)&Bh[sm][sko] = *(const uint4*)(Bhg + off);
            *(uint4*)&Bl[sm][sko] = *(const uint4*)(Blg + off);
        }
        __syncthreads();

        unsigned ah[4][4], bh[4][2];
#pragma unroll
        for (int mt = 0; mt < 4; mt++) {
            int m = wm + mt * 16 + r;
            ah[mt][0] = *(const unsigned*)&Ah[m][2 * c];
            ah[mt][1] = *(const unsigned*)&Ah[m + 8][2 * c];
            ah[mt][2] = *(const unsigned*)&Ah[m][2 * c + 8];
            ah[mt][3] = *(const unsigned*)&Ah[m + 8][2 * c + 8];
        }
#pragma unroll
        for (int nt = 0; nt < 4; nt++) {
            int n = wn + nt * 8 + r;
            bh[nt][0] = *(const unsigned*)&Bh[n][2 * c];
            bh[nt][1] = *(const unsigned*)&Bh[n][2 * c + 8];
        }
#pragma unroll
        for (int mt = 0; mt < 4; mt++)
#pragma unroll
            for (int nt = 0; nt < 4; nt++) mma16(acc[mt][nt], ah[mt], bh[nt]);
        // hi(A) * lo(B)
        {
            unsigned bl[4][2];
#pragma unroll
            for (int nt = 0; nt < 4; nt++) {
                int n = wn + nt * 8 + r;
                bl[nt][0] = *(const unsigned*)&Bl[n][2 * c];
                bl[nt][1] = *(const unsigned*)&Bl[n][2 * c + 8];
            }
#pragma unroll
            for (int mt = 0; mt < 4; mt++)
#pragma unroll
                for (int nt = 0; nt < 4; nt++) mma16(acc[mt][nt], ah[mt], bl[nt]);
        }
        __syncthreads();
    }
#pragma unroll
    for (int mt = 0; mt < 4; mt++)
#pragma unroll
        for (int nt = 0; nt < 4; nt++) {
            int m0 = bm + wm + mt * 16 + r;
            int n0 = bn + wn + nt * 8 + 2 * c;
            *(__half2*)(C + (size_t)m0 * N + n0) =
                __floats2half2_rn(acc[mt][nt][0], acc[mt][nt][1]);
            *(__half2*)(C + (size_t)(m0 + 8) * N + n0) =
                __floats2half2_rn(acc[mt][nt][2], acc[mt][nt][3]);
        }
}

// ---------------- scatter for COUT=64 (fp16 H) with FUSED bias GEMM ------------
__global__ __launch_bounds__(256) void scatter64F(const EdgeRec* __restrict__ recs,
                                                  const int* __restrict__ offs,
                                                  const __half* __restrict__ H,
                                                  const float* __restrict__ Xb,
                                                  const float* __restrict__ F, int KB,
                                                  const float* __restrict__ resid,
                                                  float* __restrict__ out) {
    __shared__ float Fs[96 * 64];
    for (int t = threadIdx.x; t < KB * 64; t += 256) Fs[t] = F[t];
    __syncthreads();
    int i = blockIdx.x * 8 + (threadIdx.x >> 5);
    int lane = threadIdx.x & 31;
    if (i >= NF) return;
    int c2 = 2 * lane;
    float y0 = 0.f, y1 = 0.f;
    int pe = offs[i + 1];
#pragma unroll 2
    for (int p = offs[i]; p < pe; ++p) {
        int4 rv = *(const int4*)&recs[p];
        float tu = __int_as_float(rv.y), tv = __int_as_float(rv.z);
        int iu = min(max((int)tu, 0), 6);
        int iv = min(max((int)tv, 0), 6);
        const __half* hb = H + (size_t)rv.x * 4096 + c2;
#pragma unroll
        for (int du = 0; du <= 1; du++) {
            float wu = fmaxf(0.f, 1.f - fabsf(tu - (float)(iu + du)));
#pragma unroll
            for (int dv = 0; dv <= 1; dv++) {
                float w = wu * fmaxf(0.f, 1.f - fabsf(tv - (float)(iv + dv)));
                float2 f = __half22float2(
                    *(const __half2*)(hb + ((iu + du) * 8 + (iv + dv)) * 64));
                y0 += w * f.x;
                y1 += w * f.y;
            }
        }
    }
    const float* x = Xb + (size_t)i * KB;
    for (int cc = 0; cc < KB; cc++) {
        float xv = x[cc];
        y0 += xv * Fs[cc * 64 + c2];
        y1 += xv * Fs[cc * 64 + c2 + 1];
    }
    if (resid) { y0 += resid[i * 64 + c2]; y1 += resid[i * 64 + c2 + 1]; }
    out[i * 64 + c2]     = fmaxf(y0, 0.f);
    out[i * 64 + c2 + 1] = fmaxf(y1, 0.f);
}

// ---------------- scatter for COUT=2 (fp16 H), precomputed bias, no relu -------
__global__ __launch_bounds__(256) void scatter2(const EdgeRec* __restrict__ recs,
                                                const int* __restrict__ offs,
                                                const __half* __restrict__ H,
                                                const float* __restrict__ bias,
                                                float* __restrict__ out) {
    int i = blockIdx.x * 8 + (threadIdx.x >> 5);
    int lane = threadIdx.x & 31;
    if (i >= NF) return;
    float y0 = 0.f, y1 = 0.f;
    int pe = offs[i + 1];
    for (int p = offs[i] + lane; p < pe; p += 32) {
        int4 rv = *(const int4*)&recs[p];
        float tu = __int_as_float(rv.y), tv = __int_as_float(rv.z);
        int iu = min(max((int)tu, 0), 6);
        int iv = min(max((int)tv, 0), 6);
        const __half* hb = H + (size_t)rv.x * 128;
#pragma unroll
        for (int du = 0; du <= 1; du++) {
            float wu = fmaxf(0.f, 1.f - fabsf(tu - (float)(iu + du)));
#pragma unroll
            for (int dv = 0; dv <= 1; dv++) {
                float w = wu * fmaxf(0.f, 1.f - fabsf(tv - (float)(iv + dv)));
                float2 f = __half22float2(
                    *(const __half2*)(hb + ((iu + du) * 8 + (iv + dv)) * 2));
                y0 += w * f.x;
                y1 += w * f.y;
            }
        }
    }
#pragma unroll
    for (int o = 16; o > 0; o >>= 1) {
        y0 += __shfl_xor_sync(0xffffffffu, y0, o);
        y1 += __shfl_xor_sync(0xffffffffu, y1, o);
    }
    if (lane == 0) {
        out[i * 2]     = y0 + bias[i * 2];
        out[i * 2 + 1] = y1 + bias[i * 2 + 1];
    }
}

// ---------------- launch ----------------
extern "C" void kernel_launch(void* const* d_in, const int* in_sizes, int n_in,
                              void* d_out, int out_size) {
    const float* fp    = (const float*)d_in[0];
    const float* bp    = (const float*)d_in[1];
    const float* ff    = (const float*)d_in[2];
    const float* bfeat = (const float*)d_in[3];
    const float* sup   = (const float*)d_in[4];
    const int*   fi    = (const int*)d_in[5];
    const int*   fj    = (const int*)d_in[6];
    const int*   bfm   = (const int*)d_in[7];
    const int*   bb    = (const int*)d_in[8];
    const float* W0    = (const float*)d_in[9];
    const float* W1    = (const float*)d_in[10];
    const float* W2    = (const float*)d_in[11];
    const float* W3    = (const float*)d_in[12];
    const float* W4    = (const float*)d_in[13];
    const float* fc0   = (const float*)d_in[14];
    const float* fc1   = (const float*)d_in[15];
    const float* fc2   = (const float*)d_in[16];
    const float* fc3   = (const float*)d_in[17];
    float* out = (float*)d_out;

    __half *H, *Wh, *Wl;
    float *X1, *X2, *X3, *Yb;
    int *cntf, *offf, *curf, *cntb, *offb, *curb;
    EdgeRec *ef, *eb;
    cudaGetSymbolAddress((void**)&H,  g_H);
    cudaGetSymbolAddress((void**)&Wh, g_Wh);
    cudaGetSymbolAddress((void**)&Wl, g_Wl);
    cudaGetSymbolAddress((void**)&X1, g_X1);
    cudaGetSymbolAddress((void**)&X2, g_X2);
    cudaGetSymbolAddress((void**)&X3, g_X3);
    cudaGetSymbolAddress((void**)&Yb, g_Yb);
    cudaGetSymbolAddress((void**)&cntf, g_cntf);
    cudaGetSymbolAddress((void**)&offf, g_offf);
    cudaGetSymbolAddress((void**)&curf, g_curf);
    cudaGetSymbolAddress((void**)&cntb, g_cntb);
    cudaGetSymbolAddress((void**)&offb, g_offb);
    cudaGetSymbolAddress((void**)&curb, g_curb);
    cudaGetSymbolAddress((void**)&ef, g_ef);
    cudaGetSymbolAddress((void**)&eb, g_eb);

    // CSR build (by target)
    resetCnt<<<64, 256>>>(cntf, cntb);
    histAll<<<(EF + EB) / 256, 256>>>(fi, bfm, cntf, cntb);
    scan2<<<2, 1024>>>(cntf, offf, curf, cntb, offb, curb);
    buildAll<<<(EF + EB) / 256, 256>>>(fi, fj, bfm, bb, fp, bp, sup,
                                       curf, ef, curb, eb);

    // ---- layer 1: X1 = [relu(ff@fc0) | relu(conv W0) | relu(conv W1)] ----
    conv4<<<NF / 8, 256>>>(ef, offf, ff,    W0, ff,              fc0,             X1, 32);
    conv4<<<NF / 8, 256>>>(eb, offb, bfeat, W1, (const float*)0, (const float*)0, X1, 64);

    // ---- layer 2: X2 = relu(conv(X1,W2) + X1@fc1) ----
    transWh<<<(96 * 4096) / 256, 256>>>(W2, Wh, Wl, 96, 64, 96 * 4096);
    fp16gemm<<<dim3(32, 128), 256>>>(NF, 4096, 96, X1, Wh, Wl, H);
    scatter64F<<<NF / 8, 256>>>(ef, offf, H, X1, fc1, 96, (const float*)0, X2);

    // ---- layer 3: X3 = relu(conv(X2,W3) + X2@fc2 + X2) ----
    transWh<<<(64 * 4096) / 256, 256>>>(W3, Wh, Wl, 64, 64, 64 * 4096);
    fp16gemm<<<dim3(32, 128), 256>>>(NF, 4096, 64, X2, Wh, Wl, H);
    scatter64F<<<NF / 8, 256>>>(ef, offf, H, X2, fc2, 64, X2, X3);

    // ---- layer 4: out = conv(X3,W4) + X3@fc3 (no relu) ----
    transWh<<<(64 * 128) / 256 + 1, 256>>>(W4, Wh, Wl, 64, 2, 64 * 64 * 2);
    fp16gemm<<<dim3(1, 128), 256>>>(NF, 128, 64, X3, Wh, Wl, H);
    gemmBias<<<(NF * 2) / 256, 256>>>(X3, fc3, Yb, 64, 2, NF * 2);
    scatter2<<<NF / 8, 256>>>(ef, offf, H, Yb, out);

    (void)in_sizes; (void)n_in; (void)out_size;
}